// round 13
// baseline (speedup 1.0000x reference)
#include <cuda_runtime.h>
#include <cuda_fp16.h>
#include <cstdint>

// ============================================================================
// DirectionalConv3d via mma.sync FP16 (compute_103-safe).
//   x: [8, 64, 32, 32, 32] fp32; 7 weights [64,64]; out[b,o,n] =
//     sum_d sum_i W_d[o,i] * x[b,i, n+shift_d]   (zero outside domain)
//
// R12 change vs R9 (84.0us; k_gemm 61.3us, L1=62% tensor=39% issue=29%):
// software-pipeline the 14 (direction, kt2) stages with one-stage-ahead A
// prefetch (double buffer), closed-form per-direction addressing (scalar base
// + static fragment offsets + validity bitmask), masked dead t-directions
// (no loop irregularity), direction order self,c+-,r+-,t+- for L1 line reuse.
// Byte budget unchanged; exposed LDG latency hidden -> L1-throughput-bound.
//
// x scratch layout (uint4 units):  g_x4[ ((b*4096 + n8)*8 + u)*8 + p ]
//   n8 = n>>3, p = n&7, u = kt2*4 + tg
//   uint4 = { pair(kt=2kt2 ,h=0), pair(kt=2kt2 ,h=1),
//             pair(kt=2kt2+1,h=0), pair(kt=2kt2+1,h=1) }
//   pair(kt,h) = fp16x2 of channels (16kt + 2tg + 8h, +1)
// B layout (uint4): g_b4[ (d*2+kt2)*256 + n*4 + tg ]  (n = out channel)
// ============================================================================

#define NSP    32768
#define NTILES 512                    // 8 b * 32 t * 2 r-halves
#define GRID   128                    // 4 consecutive tiles per CTA
#define NTHR   256
#define SMEM_BYTES (3584 * 16)        // 56 KB weights

__device__ __align__(16) uint4 g_x4[8u * 4096 * 64];   // 32 MB
__device__ __align__(16) uint4 g_b4[3584];             // 56 KB

static __device__ __forceinline__ void mma_f16(
    float* c, uint32_t a0, uint32_t a1, uint32_t a2, uint32_t a3,
    uint32_t b0, uint32_t b1)
{
    asm volatile(
        "mma.sync.aligned.m16n8k16.row.col.f32.f16.f16.f32 "
        "{%0,%1,%2,%3}, {%4,%5,%6,%7}, {%8,%9}, {%0,%1,%2,%3};"
        : "+f"(c[0]), "+f"(c[1]), "+f"(c[2]), "+f"(c[3])
        : "r"(a0), "r"(a1), "r"(a2), "r"(a3), "r"(b0), "r"(b1));
}

static __device__ __forceinline__ uint32_t packh2(float a, float b) {
    __half2 h = __floats2half2_rn(a, b);
    return *reinterpret_cast<uint32_t*>(&h);
}

// ============================================================================
// k_prep: blocks [0,4096) split x (64-point chunks, SMEM transpose);
//         blocks [4096, 4110) permute weights.
// ============================================================================
__global__ void __launch_bounds__(256) k_prep(
    const float* __restrict__ x,
    const float* __restrict__ w0, const float* __restrict__ w1,
    const float* __restrict__ w2, const float* __restrict__ w3,
    const float* __restrict__ w4, const float* __restrict__ w5,
    const float* __restrict__ w6)
{
    __shared__ float sm[64][65];
    int blk = blockIdx.x;
    int tid = threadIdx.x;

    if (blk < 4096) {
        int b  = blk >> 9;
        int nc = (blk & 511) << 6;                     // chunk base point
        const float* px = x + (((size_t)b) << 21) + nc;
        #pragma unroll
        for (int i = tid; i < 4096; i += 256) {
            int k = i >> 6, nn = i & 63;
            sm[k][nn] = __ldg(px + (((size_t)k) << 15) + nn);
        }
        __syncthreads();
        #pragma unroll
        for (int i = tid; i < 512; i += 256) {
            int p   = i & 7;
            int u   = (i >> 3) & 7;
            int np  = ((i >> 6) << 3) | p;
            int kt2 = u >> 2, tg = u & 3;
            int k0  = 32 * kt2 + 2 * tg;
            int k1  = k0 + 16;
            uint4 v;
            v.x = packh2(sm[k0][np],     sm[k0 + 1][np]);
            v.y = packh2(sm[k0 + 8][np], sm[k0 + 9][np]);
            v.z = packh2(sm[k1][np],     sm[k1 + 1][np]);
            v.w = packh2(sm[k1 + 8][np], sm[k1 + 9][np]);
            int n8 = (nc >> 3) + (np >> 3);
            g_x4[((((size_t)b << 12) + n8) << 6) + (u << 3) + p] = v;
        }
    } else {
        int i = (blk - 4096) * 256 + tid;
        if (i < 3584) {
            int d   = i / 512;
            int rem = i & 511;
            int kt2 = rem >> 8;
            int n   = (rem >> 2) & 63;
            int tg  = rem & 3;
            const float* w = (d == 0) ? w0 : (d == 1) ? w1 : (d == 2) ? w2 :
                             (d == 3) ? w3 : (d == 4) ? w4 : (d == 5) ? w5 : w6;
            const float* wr = w + n * 64;
            int k0 = 32 * kt2 + 2 * tg;
            int k1 = k0 + 16;
            uint4 v;
            v.x = packh2(wr[k0],     wr[k0 + 1]);
            v.y = packh2(wr[k0 + 8], wr[k0 + 9]);
            v.z = packh2(wr[k1],     wr[k1 + 1]);
            v.w = packh2(wr[k1 + 8], wr[k1 + 9]);
            g_b4[i] = v;
        }
    }
}

// ============================================================================
// k_gemm: persistent, 128 CTAs x 4 consecutive tiles.
//   Tile = (b, t, 16 r x 32 c) = 512 points; 8 warps, warp M=64 N=64 K=64.
//   14 software-pipelined stages (7 dirs x 2 kt2), double-buffered A.
//   Fragment f (0..7): row = f>>2 (r-row rbase+row+dr), cgrp = f&3; A frags
//   for MMA mt use f = 2mt (m=mt*16+g) and f = 2mt+1 (m=mt*16+g+8).
// ============================================================================
__global__ void __launch_bounds__(NTHR, 1) k_gemm(float* __restrict__ out)
{
    extern __shared__ uint4 sB[];      // 3584 uint4
    const int tid  = threadIdx.x;
    const int w    = tid >> 5;
    const int lane = tid & 31;
    const int g    = lane >> 2;
    const int tg   = lane & 3;

    #pragma unroll
    for (int i = tid; i < 3584; i += NTHR)
        sB[i] = __ldg(g_b4 + i);
    __syncthreads();

    // direction processing order: self, c-, c+, r-, r+, t-, t+
    // (PD = weight index; shifts per that weight)
    const int PD [7] = {0,  5,  6,  3,  4,  1,  2};
    const int PDT[7] = {0,  0,  0,  0,  0, -1,  1};
    const int PDR[7] = {0,  0,  0, -1,  1,  0,  0};
    const int PDC[7] = {0, -1,  1,  0,  0,  0,  0};

    #pragma unroll 1
    for (int it = 0; it < 4; ++it) {
        int tile = blockIdx.x * 4 + it;
        int rq = tile & 1;
        int t  = (tile >> 1) & 31;
        int b  = tile >> 6;
        int rbase = rq * 16 + w * 2;
        int n0 = t * 1024 + rbase * 32;

        float acc[4][8][4];
        #pragma unroll
        for (int mt = 0; mt < 4; mt++)
            #pragma unroll
            for (int nt = 0; nt < 8; nt++)
                #pragma unroll
                for (int q = 0; q < 4; q++) acc[mt][nt][q] = 0.f;

        uint4 A[2][8];
        int base = 0;
        unsigned vm = 0;

        // --- addressing for direction (dt,dr,dc): scalar base + 8-bit mask
        auto mk = [&](int dt, int dr, int dc) {
            int ts = t + dt;
            int r0 = rbase + dr;
            bool tsv = (unsigned)ts < 32u;
            bool rv0 = tsv && ((unsigned)r0 < 32u);
            bool rv1 = tsv && ((unsigned)(r0 + 1) < 32u);
            int pofs = (dc == 0) ? g
                     : (dc > 0) ? ((g == 7) ? 64 : g + 1)
                                : ((g == 0) ? 7 - 64 : g - 1);
            base = (((b << 12) + ts * 128 + r0 * 4) << 6) + (tg << 3) + pofs;
            int ck = (dc > 0 && g == 7) ? 3 : ((dc < 0 && g == 0) ? 0 : -1);
            vm = 0;
            #pragma unroll
            for (int f = 0; f < 8; f++) {
                bool v = ((f >> 2) ? rv1 : rv0) && ((f & 3) != ck);
                vm |= (unsigned)v << f;
            }
        };

        auto loadA = [&](uint4* Ab, int kt2) {
            const uint4 z4 = make_uint4(0u, 0u, 0u, 0u);
            #pragma unroll
            for (int f = 0; f < 8; f++) {
                bool v = (vm >> f) & 1u;
                Ab[f] = v ? __ldg(g_x4 + (base + (f & 3) * 64
                                          + (f >> 2) * 256 + kt2 * 32))
                          : z4;
            }
        };

        // prologue
        mk(PDT[0], PDR[0], PDC[0]);
        loadA(A[0], 0);

        #pragma unroll
        for (int s = 0; s < 14; ++s) {
            const int di  = s >> 1;
            const int kt2 = s & 1;
            const int d   = PD[di];

            // prefetch next stage's A into the other buffer
            if (s < 13) {
                if (kt2 == 0) {
                    loadA(A[(s + 1) & 1], 1);
                } else {
                    mk(PDT[di + 1], PDR[di + 1], PDC[di + 1]);
                    loadA(A[(s + 1) & 1], 0);
                }
            }

            const uint4* Ac = A[s & 1];
            #pragma unroll
            for (int nh = 0; nh < 2; nh++) {
                uint4 bf[4];
                #pragma unroll
                for (int j = 0; j < 4; j++)
                    bf[j] = sB[(d * 2 + kt2) * 256
                               + ((nh * 4 + j) * 8 + g) * 4 + tg];
                #pragma unroll
                for (int mt = 0; mt < 4; mt++)
                    #pragma unroll
                    for (int j = 0; j < 4; j++) {
                        float* a = acc[mt][nh * 4 + j];
                        mma_f16(a, Ac[2*mt].x, Ac[2*mt+1].x,
                                   Ac[2*mt].y, Ac[2*mt+1].y,
                                   bf[j].x, bf[j].y);
                        mma_f16(a, Ac[2*mt].z, Ac[2*mt+1].z,
                                   Ac[2*mt].w, Ac[2*mt+1].w,
                                   bf[j].z, bf[j].w);
                    }
            }
        }

        // epilogue: out[b][o][n0 + m]
        #pragma unroll
        for (int mt = 0; mt < 4; mt++) {
            #pragma unroll
            for (int nt = 0; nt < 8; nt++) {
                int o0 = nt * 8 + tg * 2;
                int m0 = mt * 16 + g;
                float* p = out + ((size_t)(b * 64 + o0) << 15) + n0 + m0;
                p[0]             = acc[mt][nt][0];
                p[1 << 15]       = acc[mt][nt][1];
                p[8]             = acc[mt][nt][2];
                p[(1 << 15) + 8] = acc[mt][nt][3];
            }
        }
    }
}

// ============================================================================
// Launch
// ============================================================================
extern "C" void kernel_launch(void* const* d_in, const int* in_sizes, int n_in,
                              void* d_out, int out_size)
{
    (void)in_sizes; (void)n_in; (void)out_size;
    static bool attr_done = false;
    if (!attr_done) {
        cudaFuncSetAttribute(k_gemm, cudaFuncAttributeMaxDynamicSharedMemorySize,
                             SMEM_BYTES);
        attr_done = true;
    }

    k_prep<<<4096 + 14, 256>>>(
        (const float*)d_in[0],
        (const float*)d_in[1], (const float*)d_in[2], (const float*)d_in[3],
        (const float*)d_in[4], (const float*)d_in[5], (const float*)d_in[6],
        (const float*)d_in[7]);

    k_gemm<<<GRID, NTHR, SMEM_BYTES>>>((float*)d_out);
}